// round 4
// baseline (speedup 1.0000x reference)
#include <cuda_runtime.h>
#include <cstdint>

#define D_SUB 8
#define KC 128
#define SUB 16
#define EMB 128

#define K1_BLOCKS 256
#define K1_THREADS 256
#define K1_WARPS (K1_BLOCKS * K1_THREADS / 32)   // 2048
#define PSTRIDE 2320                              // 8*(256 M +16 w +16 S1) + 16 p/q
#define K2A_BLOCKS 64
#define WARPS_PER_CHUNK (K1_WARPS / K2A_BLOCKS)   // 32

// scratch (no allocation allowed -> __device__ globals)
__device__ float g_part[(size_t)K1_WARPS * PSTRIDE];
__device__ float g_part2[(size_t)K2A_BLOCKS * PSTRIDE];
__device__ float g_G[KC];          // s_k
__device__ float g_B[D_SUB * KC];  // -s_k*(normc_dk + mean_k)

// ---------- packed f32x2 helpers ----------
__device__ __forceinline__ unsigned long long pack2(float lo, float hi) {
    unsigned long long r;
    asm("mov.b64 %0, {%1, %2};" : "=l"(r) : "f"(lo), "f"(hi));
    return r;
}
__device__ __forceinline__ void fma2(unsigned long long& d, unsigned long long a, unsigned long long b) {
    asm("fma.rn.f32x2 %0, %1, %2, %0;" : "+l"(d) : "l"(a), "l"(b));
}
__device__ __forceinline__ unsigned long long fma2i(unsigned long long a, unsigned long long b, unsigned long long c) {
    unsigned long long r;
    asm("fma.rn.f32x2 %0, %1, %2, %3;" : "=l"(r) : "l"(a), "l"(b), "l"(c));
    return r;
}
__device__ __forceinline__ unsigned long long mul2(unsigned long long a, unsigned long long b) {
    unsigned long long r;
    asm("mul.rn.f32x2 %0, %1, %2;" : "=l"(r) : "l"(a), "l"(b));
    return r;
}
__device__ __forceinline__ unsigned long long add2(unsigned long long a, unsigned long long b) {
    unsigned long long r;
    asm("add.rn.f32x2 %0, %1, %2;" : "=l"(r) : "l"(a), "l"(b));
    return r;
}
__device__ __forceinline__ float lo2(unsigned long long v) { return __uint_as_float((unsigned)v); }
__device__ __forceinline__ float hi2(unsigned long long v) { return __uint_as_float((unsigned)(v >> 32)); }

// =====================================================================
// Kernel 1: per-warp moment accumulation.
// lane = 4*g + q : g = subspace d (0..7), q = row-quarter of M_d (0..3)
// =====================================================================
__global__ void k1_moments(const int* __restrict__ ids,
                           const float* __restrict__ wemb, int NI)
{
    int warp = (blockIdx.x * blockDim.x + threadIdx.x) >> 5;
    int lane = threadIdx.x & 31;
    int g = lane >> 2;   // subspace
    int q = lane & 3;    // row quarter

    unsigned long long M2[4][8];
#pragma unroll
    for (int r = 0; r < 4; r++)
#pragma unroll
        for (int p = 0; p < 8; p++) M2[r][p] = 0ull;
    float wv[4] = {0.f, 0.f, 0.f, 0.f};
    float s1[4] = {0.f, 0.f, 0.f, 0.f};
    float pA = 0.f, qA = 0.f;

#pragma unroll 4
    for (int n = warp; n < NI; n += K1_WARPS) {
        int id = ids[n];
        const ulonglong2* xr = (const ulonglong2*)(wemb + (size_t)id * EMB + g * SUB);
        ulonglong2 v0 = xr[0], v1 = xr[1], v2 = xr[2], v3 = xr[3];
        unsigned long long x2[8] = {v0.x, v0.y, v1.x, v1.y, v2.x, v2.y, v3.x, v3.y};

        unsigned long long na = mul2(x2[0], x2[0]);
        unsigned long long nb = mul2(x2[1], x2[1]);
#pragma unroll
        for (int p = 2; p < 8; p += 2) { fma2(na, x2[p], x2[p]); fma2(nb, x2[p + 1], x2[p + 1]); }
        na = add2(na, nb);
        float nx = lo2(na) + hi2(na);

        // this lane's 4 rows = quarter q of the 16 elements
        unsigned long long q0 = x2[2 * q], q1 = x2[2 * q + 1];
        float rv[4] = {lo2(q0), hi2(q0), lo2(q1), hi2(q1)};
#pragma unroll
        for (int r = 0; r < 4; r++) {
            unsigned long long xd = pack2(rv[r], rv[r]);
#pragma unroll
            for (int p = 0; p < 8; p++) fma2(M2[r][p], xd, x2[p]);
            wv[r] = fmaf(rv[r], nx, wv[r]);
            s1[r] += rv[r];
        }
        if (q == 0) { pA += nx; qA = fmaf(nx, nx, qA); }
    }

    float* base = g_part + (size_t)warp * PSTRIDE + g * 288;
#pragma unroll
    for (int r = 0; r < 4; r++) {
#pragma unroll
        for (int p = 0; p < 8; p++) {
            base[(4 * q + r) * 16 + 2 * p]     = lo2(M2[r][p]);
            base[(4 * q + r) * 16 + 2 * p + 1] = hi2(M2[r][p]);
        }
        base[256 + 4 * q + r] = wv[r];
        base[272 + 4 * q + r] = s1[r];
    }
    if (q == 0) {
        g_part[(size_t)warp * PSTRIDE + 2304 + 2 * g]     = pA;
        g_part[(size_t)warp * PSTRIDE + 2304 + 2 * g + 1] = qA;
    }
}

// =====================================================================
// Kernel 2a: parallel deterministic reduction 2048 -> 64 partials
// =====================================================================
__global__ void k2a_reduce()
{
    int b = blockIdx.x;
    for (int idx = threadIdx.x; idx < PSTRIDE; idx += blockDim.x) {
        float s = 0.f;
        const float* p = g_part + (size_t)b * WARPS_PER_CHUNK * PSTRIDE + idx;
#pragma unroll 4
        for (int w = 0; w < WARPS_PER_CHUNK; w++) s += p[(size_t)w * PSTRIDE];
        g_part2[(size_t)b * PSTRIDE + idx] = s;
    }
}

// =====================================================================
// Kernel 2b: final fp64 reduce + per-k BN coefficients.
// =====================================================================
__global__ void k2b_coeffs(const float* __restrict__ cent, int NI)
{
    __shared__ double mom[PSTRIDE];
    int tid = threadIdx.x;
    for (int idx = tid; idx < PSTRIDE; idx += blockDim.x) {
        double s = 0.0;
        for (int b = 0; b < K2A_BLOCKS; b++)
            s += (double)g_part2[(size_t)b * PSTRIDE + idx];
        mom[idx] = s;
    }
    __syncthreads();

    if (tid < KC) {
        int k = tid;
        double sum = 0.0, ssq = 0.0;
        double ncs[D_SUB];
        double cnt = (double)NI;
        for (int d = 0; d < D_SUB; d++) {
            const float* c = cent + ((size_t)d * KC + k) * SUB;
            double cv[16];
#pragma unroll
            for (int i = 0; i < 16; i++) cv[i] = (double)c[i];
            double nc = 0.0, dotS = 0.0, dotw = 0.0, quad = 0.0;
            const double* Md = mom + d * 288;
#pragma unroll
            for (int i = 0; i < 16; i++) {
                nc   += cv[i] * cv[i];
                dotw += Md[256 + i] * cv[i];
                dotS += Md[272 + i] * cv[i];
                double row = 0.0;
#pragma unroll
                for (int j = 0; j < 16; j++) row += Md[i * 16 + j] * cv[j];
                quad += cv[i] * row;
            }
            ncs[d] = nc;
            double p = mom[2304 + 2 * d], qq = mom[2304 + 2 * d + 1];
            sum += 2.0 * dotS - p - cnt * nc;
            ssq += 4.0 * quad - 4.0 * (dotw + nc * dotS) + (qq + 2.0 * nc * p + cnt * nc * nc);
        }
        double tot  = cnt * (double)D_SUB;
        double mean = sum / tot;
        double var  = ssq / tot - mean * mean;
        double s    = 1.0 / sqrt(var + 0.001);
        g_G[k] = (float)s;
        for (int d = 0; d < D_SUB; d++)
            g_B[d * KC + k] = (float)(-s * (ncs[d] + mean));
    }
}

// =====================================================================
// Kernel 3: thread-per-(n,d) x 2 tokens, 2*centroids in SMEM.
// Dual accumulators halve the FMA2 dependency chain; -||x||^2 folded
// into the first FMA2's addend; score = s*dotsum + B (1 FFMA).
// =====================================================================
__global__ void __launch_bounds__(256, 3)
k3_assign(const int* __restrict__ ids,
          const float* __restrict__ wemb,
          const float* __restrict__ cent,
          float* __restrict__ out, int NI)
{
    __shared__ float cs[KC][20];   // [k]: 2*c[16], s, B, pad2

    int tid = threadIdx.x;
    int d = blockIdx.y;

    for (int i = tid; i < KC * SUB; i += 256) {
        int k = i >> 4, j = i & 15;
        cs[k][j] = 2.0f * cent[((size_t)(d * KC + k)) * SUB + j];
    }
    if (tid < KC) {
        cs[tid][16] = g_G[tid];
        cs[tid][17] = g_B[d * KC + tid];
    }
    __syncthreads();

    int base = blockIdx.x * 512 + tid;
    int n[2] = {base, base + 256};

    unsigned long long X[2][8];
    unsigned long long nxp[2];
    float best[2];
    int bk[2];
    bool valid[2];

#pragma unroll
    for (int t = 0; t < 2; t++) {
        valid[t] = (n[t] < NI);
        int id = valid[t] ? ids[n[t]] : 0;
        const ulonglong2* xp = (const ulonglong2*)(wemb + (size_t)id * EMB + d * SUB);
        ulonglong2 v0 = xp[0], v1 = xp[1], v2 = xp[2], v3 = xp[3];
        X[t][0] = v0.x; X[t][1] = v0.y; X[t][2] = v1.x; X[t][3] = v1.y;
        X[t][4] = v2.x; X[t][5] = v2.y; X[t][6] = v3.x; X[t][7] = v3.y;
        unsigned long long na = mul2(X[t][0], X[t][0]);
        unsigned long long nb = mul2(X[t][1], X[t][1]);
#pragma unroll
        for (int p = 2; p < 8; p += 2) { fma2(na, X[t][p], X[t][p]); fma2(nb, X[t][p + 1], X[t][p + 1]); }
        na = add2(na, nb);
        nxp[t] = pack2(-(lo2(na) + hi2(na)), 0.0f);
        best[t] = -3.4e38f;
        bk[t] = 0;
    }

#pragma unroll 4
    for (int k = 0; k < KC; k++) {
        const ulonglong2* cp = (const ulonglong2*)&cs[k][0];
        ulonglong2 c0 = cp[0], c1 = cp[1], c2v = cp[2], c3 = cp[3];
        unsigned long long C[8] = {c0.x, c0.y, c1.x, c1.y, c2v.x, c2v.y, c3.x, c3.y};
        float2 sb = *(const float2*)&cs[k][16];
#pragma unroll
        for (int t = 0; t < 2; t++) {
            unsigned long long a0 = fma2i(X[t][0], C[0], nxp[t]);   // x*2c - ||x||^2 seed
            unsigned long long a1 = mul2(X[t][1], C[1]);
            fma2(a0, X[t][2], C[2]);
            fma2(a1, X[t][3], C[3]);
            fma2(a0, X[t][4], C[4]);
            fma2(a1, X[t][5], C[5]);
            fma2(a0, X[t][6], C[6]);
            fma2(a1, X[t][7], C[7]);
            a0 = add2(a0, a1);
            float ds = lo2(a0) + hi2(a0);
            float sc = fmaf(sb.x, ds, sb.y);
            if (sc > best[t]) { best[t] = sc; bk[t] = k; }
        }
    }

#pragma unroll
    for (int t = 0; t < 2; t++) {
        if (!valid[t]) continue;
        const float4* cg = (const float4*)&cs[bk[t]][0];
        float* op = out + (size_t)n[t] * EMB + d * SUB;
#pragma unroll
        for (int i = 0; i < 4; i++) {
            float4 cw = cg[i];
            float x0 = lo2(X[t][2 * i]),     x1 = hi2(X[t][2 * i]);
            float x2f = lo2(X[t][2 * i + 1]), x3 = hi2(X[t][2 * i + 1]);
            float4 o;
            o.x = __fadd_rn(x0,  __fsub_rn(0.5f * cw.x, x0));
            o.y = __fadd_rn(x1,  __fsub_rn(0.5f * cw.y, x1));
            o.z = __fadd_rn(x2f, __fsub_rn(0.5f * cw.z, x2f));
            o.w = __fadd_rn(x3,  __fsub_rn(0.5f * cw.w, x3));
            ((float4*)op)[i] = o;
        }
    }
}

extern "C" void kernel_launch(void* const* d_in, const int* in_sizes, int n_in,
                              void* d_out, int out_size)
{
    const int*   ids  = (const int*)d_in[0];
    const float* wemb = (const float*)d_in[1];
    const float* cent = (const float*)d_in[2];
    float*       out  = (float*)d_out;
    int NI = in_sizes[0];   // 131072

    k1_moments<<<K1_BLOCKS, K1_THREADS>>>(ids, wemb, NI);
    k2a_reduce<<<K2A_BLOCKS, 256>>>();
    k2b_coeffs<<<1, 256>>>(cent, NI);

    dim3 g3((NI + 511) / 512, D_SUB);
    k3_assign<<<g3, 256>>>(ids, wemb, cent, out, NI);
}

// round 5
// speedup vs baseline: 1.0850x; 1.0850x over previous
#include <cuda_runtime.h>
#include <cstdint>

#define D_SUB 8
#define KC 128
#define SUB 16
#define EMB 128

#define K1_BLOCKS 256
#define K1_THREADS 256
#define K1_WARPS (K1_BLOCKS * K1_THREADS / 32)   // 2048
#define PSTRIDE 2320                              // 8*(256 M +16 w +16 S1) + 16 p/q
#define K2A_BLOCKS 64
#define WARPS_PER_CHUNK (K1_WARPS / K2A_BLOCKS)   // 32

// scratch (no allocation allowed -> __device__ globals)
__device__ float  g_part[(size_t)K1_WARPS * PSTRIDE];
__device__ float  g_part2[(size_t)K2A_BLOCKS * PSTRIDE];
__device__ double g_mom[PSTRIDE];
__device__ double g_sumd[D_SUB * KC];
__device__ double g_ssqd[D_SUB * KC];
__device__ double g_ncv[D_SUB * KC];
__device__ float  g_G[KC];          // s_k
__device__ float  g_B[D_SUB * KC];  // -s_k*(normc_dk + mean_k)

// ---------- packed f32x2 helpers ----------
__device__ __forceinline__ unsigned long long pack2(float lo, float hi) {
    unsigned long long r;
    asm("mov.b64 %0, {%1, %2};" : "=l"(r) : "f"(lo), "f"(hi));
    return r;
}
__device__ __forceinline__ void fma2(unsigned long long& d, unsigned long long a, unsigned long long b) {
    asm("fma.rn.f32x2 %0, %1, %2, %0;" : "+l"(d) : "l"(a), "l"(b));
}
__device__ __forceinline__ unsigned long long fma2i(unsigned long long a, unsigned long long b, unsigned long long c) {
    unsigned long long r;
    asm("fma.rn.f32x2 %0, %1, %2, %3;" : "=l"(r) : "l"(a), "l"(b), "l"(c));
    return r;
}
__device__ __forceinline__ unsigned long long mul2(unsigned long long a, unsigned long long b) {
    unsigned long long r;
    asm("mul.rn.f32x2 %0, %1, %2;" : "=l"(r) : "l"(a), "l"(b));
    return r;
}
__device__ __forceinline__ unsigned long long add2(unsigned long long a, unsigned long long b) {
    unsigned long long r;
    asm("add.rn.f32x2 %0, %1, %2;" : "=l"(r) : "l"(a), "l"(b));
    return r;
}
__device__ __forceinline__ float lo2(unsigned long long v) { return __uint_as_float((unsigned)v); }
__device__ __forceinline__ float hi2(unsigned long long v) { return __uint_as_float((unsigned)(v >> 32)); }

// =====================================================================
// Kernel 1: per-warp moment accumulation.
// lane = 4*g + q : g = subspace d (0..7), q = row-quarter of M_d (0..3)
// =====================================================================
__global__ void k1_moments(const int* __restrict__ ids,
                           const float* __restrict__ wemb, int NI)
{
    int warp = (blockIdx.x * blockDim.x + threadIdx.x) >> 5;
    int lane = threadIdx.x & 31;
    int g = lane >> 2;   // subspace
    int q = lane & 3;    // row quarter

    unsigned long long M2[4][8];
#pragma unroll
    for (int r = 0; r < 4; r++)
#pragma unroll
        for (int p = 0; p < 8; p++) M2[r][p] = 0ull;
    float wv[4] = {0.f, 0.f, 0.f, 0.f};
    float s1[4] = {0.f, 0.f, 0.f, 0.f};
    float pA = 0.f, qA = 0.f;

#pragma unroll 2
    for (int n = warp; n < NI; n += K1_WARPS) {
        int id = ids[n];
        const ulonglong2* xr = (const ulonglong2*)(wemb + (size_t)id * EMB + g * SUB);
        ulonglong2 v0 = xr[0], v1 = xr[1], v2 = xr[2], v3 = xr[3];
        unsigned long long x2[8] = {v0.x, v0.y, v1.x, v1.y, v2.x, v2.y, v3.x, v3.y};

        unsigned long long na = mul2(x2[0], x2[0]);
        unsigned long long nb = mul2(x2[1], x2[1]);
#pragma unroll
        for (int p = 2; p < 8; p += 2) { fma2(na, x2[p], x2[p]); fma2(nb, x2[p + 1], x2[p + 1]); }
        na = add2(na, nb);
        float nx = lo2(na) + hi2(na);

        // this lane's 4 rows = quarter q of the 16 elements
        unsigned long long q0 = x2[2 * q], q1 = x2[2 * q + 1];
        float rv[4] = {lo2(q0), hi2(q0), lo2(q1), hi2(q1)};
#pragma unroll
        for (int r = 0; r < 4; r++) {
            unsigned long long xd = pack2(rv[r], rv[r]);
#pragma unroll
            for (int p = 0; p < 8; p++) fma2(M2[r][p], xd, x2[p]);
            wv[r] = fmaf(rv[r], nx, wv[r]);
            s1[r] += rv[r];
        }
        if (q == 0) { pA += nx; qA = fmaf(nx, nx, qA); }
    }

    float* base = g_part + (size_t)warp * PSTRIDE + g * 288;
#pragma unroll
    for (int r = 0; r < 4; r++) {
#pragma unroll
        for (int p = 0; p < 8; p++) {
            base[(4 * q + r) * 16 + 2 * p]     = lo2(M2[r][p]);
            base[(4 * q + r) * 16 + 2 * p + 1] = hi2(M2[r][p]);
        }
        base[256 + 4 * q + r] = wv[r];
        base[272 + 4 * q + r] = s1[r];
    }
    if (q == 0) {
        g_part[(size_t)warp * PSTRIDE + 2304 + 2 * g]     = pA;
        g_part[(size_t)warp * PSTRIDE + 2304 + 2 * g + 1] = qA;
    }
}

// =====================================================================
// Kernel 2a: parallel deterministic reduction 2048 -> 64 partials
// =====================================================================
__global__ void k2a_reduce()
{
    int b = blockIdx.x;
    for (int idx = threadIdx.x; idx < PSTRIDE; idx += blockDim.x) {
        float s = 0.f;
        const float* p = g_part + (size_t)b * WARPS_PER_CHUNK * PSTRIDE + idx;
#pragma unroll 4
        for (int w = 0; w < WARPS_PER_CHUNK; w++) s += p[(size_t)w * PSTRIDE];
        g_part2[(size_t)b * PSTRIDE + idx] = s;
    }
}

// =====================================================================
// Kernel 2b1: fp64 final moment reduce (64 partials -> g_mom), spread
// over 10 blocks.
// =====================================================================
__global__ void k2b1_reduce()
{
    int idx = blockIdx.x * 256 + threadIdx.x;
    if (idx < PSTRIDE) {
        double s = 0.0;
        for (int b = 0; b < K2A_BLOCKS; b++)
            s += (double)g_part2[(size_t)b * PSTRIDE + idx];
        g_mom[idx] = s;
    }
}

// =====================================================================
// Kernel 2b2: per-(d,k) quadratic forms. One block per subspace d,
// one thread per k. 8x the fp64 throughput of the old single block.
//  sum_dk = 2 S1.c - p_d - N*nc
//  ssq_dk = 4 c'Mc - 4(w.c + nc*S1.c) + (q_d + 2 nc p_d + N nc^2)
// =====================================================================
__global__ void k2b2_quad(const float* __restrict__ cent, int NI)
{
    __shared__ double Ms[288];
    __shared__ double pq[2];
    int d = blockIdx.x;
    int k = threadIdx.x;
    for (int i = k; i < 288; i += KC) Ms[i] = g_mom[d * 288 + i];
    if (k < 2) pq[k] = g_mom[2304 + 2 * d + k];
    __syncthreads();

    double cv[16];
    const float* c = cent + ((size_t)d * KC + k) * SUB;
#pragma unroll
    for (int i = 0; i < 16; i++) cv[i] = (double)c[i];
    double nc = 0.0, dotS = 0.0, dotw = 0.0, quad = 0.0;
#pragma unroll
    for (int i = 0; i < 16; i++) {
        nc   += cv[i] * cv[i];
        dotw += Ms[256 + i] * cv[i];
        dotS += Ms[272 + i] * cv[i];
        double row = 0.0;
#pragma unroll
        for (int j = 0; j < 16; j++) row += Ms[i * 16 + j] * cv[j];
        quad += cv[i] * row;
    }
    double cnt = (double)NI;
    double p = pq[0], qq = pq[1];
    g_sumd[d * KC + k] = 2.0 * dotS - p - cnt * nc;
    g_ssqd[d * KC + k] = 4.0 * quad - 4.0 * (dotw + nc * dotS) + (qq + 2.0 * nc * p + cnt * nc * nc);
    g_ncv[d * KC + k]  = nc;
}

// =====================================================================
// Kernel 2b3: combine over d (fixed order), BN coefficients.
// =====================================================================
__global__ void k2b3_coeffs(int NI)
{
    int k = threadIdx.x;
    double sum = 0.0, ssq = 0.0;
#pragma unroll
    for (int d = 0; d < D_SUB; d++) {
        sum += g_sumd[d * KC + k];
        ssq += g_ssqd[d * KC + k];
    }
    double tot  = (double)NI * (double)D_SUB;
    double mean = sum / tot;
    double var  = ssq / tot - mean * mean;
    double s    = 1.0 / sqrt(var + 0.001);
    g_G[k] = (float)s;
#pragma unroll
    for (int d = 0; d < D_SUB; d++)
        g_B[d * KC + k] = (float)(-s * (g_ncv[d * KC + k] + mean));
}

// =====================================================================
// Kernel 3: thread-per-(n,d) x 2 tokens, 2*centroids in SMEM.
// Dual accumulators halve the FMA2 dependency chain; -||x||^2 folded
// into the first FMA2's addend; score = s*dotsum + B (1 FFMA).
// =====================================================================
__global__ void __launch_bounds__(256, 3)
k3_assign(const int* __restrict__ ids,
          const float* __restrict__ wemb,
          const float* __restrict__ cent,
          float* __restrict__ out, int NI)
{
    __shared__ float cs[KC][20];   // [k]: 2*c[16], s, B, pad2

    int tid = threadIdx.x;
    int d = blockIdx.y;

    for (int i = tid; i < KC * SUB; i += 256) {
        int k = i >> 4, j = i & 15;
        cs[k][j] = 2.0f * cent[((size_t)(d * KC + k)) * SUB + j];
    }
    if (tid < KC) {
        cs[tid][16] = g_G[tid];
        cs[tid][17] = g_B[d * KC + tid];
    }
    __syncthreads();

    int base = blockIdx.x * 512 + tid;
    int n[2] = {base, base + 256};

    unsigned long long X[2][8];
    unsigned long long nxp[2];
    float best[2];
    int bk[2];
    bool valid[2];

#pragma unroll
    for (int t = 0; t < 2; t++) {
        valid[t] = (n[t] < NI);
        int id = valid[t] ? ids[n[t]] : 0;
        const ulonglong2* xp = (const ulonglong2*)(wemb + (size_t)id * EMB + d * SUB);
        ulonglong2 v0 = xp[0], v1 = xp[1], v2 = xp[2], v3 = xp[3];
        X[t][0] = v0.x; X[t][1] = v0.y; X[t][2] = v1.x; X[t][3] = v1.y;
        X[t][4] = v2.x; X[t][5] = v2.y; X[t][6] = v3.x; X[t][7] = v3.y;
        unsigned long long na = mul2(X[t][0], X[t][0]);
        unsigned long long nb = mul2(X[t][1], X[t][1]);
#pragma unroll
        for (int p = 2; p < 8; p += 2) { fma2(na, X[t][p], X[t][p]); fma2(nb, X[t][p + 1], X[t][p + 1]); }
        na = add2(na, nb);
        nxp[t] = pack2(-(lo2(na) + hi2(na)), 0.0f);
        best[t] = -3.4e38f;
        bk[t] = 0;
    }

#pragma unroll 4
    for (int k = 0; k < KC; k++) {
        const ulonglong2* cp = (const ulonglong2*)&cs[k][0];
        ulonglong2 c0 = cp[0], c1 = cp[1], c2v = cp[2], c3 = cp[3];
        unsigned long long C[8] = {c0.x, c0.y, c1.x, c1.y, c2v.x, c2v.y, c3.x, c3.y};
        float2 sb = *(const float2*)&cs[k][16];
#pragma unroll
        for (int t = 0; t < 2; t++) {
            unsigned long long a0 = fma2i(X[t][0], C[0], nxp[t]);   // x*2c - ||x||^2 seed
            unsigned long long a1 = mul2(X[t][1], C[1]);
            fma2(a0, X[t][2], C[2]);
            fma2(a1, X[t][3], C[3]);
            fma2(a0, X[t][4], C[4]);
            fma2(a1, X[t][5], C[5]);
            fma2(a0, X[t][6], C[6]);
            fma2(a1, X[t][7], C[7]);
            a0 = add2(a0, a1);
            float ds = lo2(a0) + hi2(a0);
            float sc = fmaf(sb.x, ds, sb.y);
            if (sc > best[t]) { best[t] = sc; bk[t] = k; }
        }
    }

#pragma unroll
    for (int t = 0; t < 2; t++) {
        if (!valid[t]) continue;
        const float4* cg = (const float4*)&cs[bk[t]][0];
        float* op = out + (size_t)n[t] * EMB + d * SUB;
#pragma unroll
        for (int i = 0; i < 4; i++) {
            float4 cw = cg[i];
            float x0 = lo2(X[t][2 * i]),     x1 = hi2(X[t][2 * i]);
            float x2f = lo2(X[t][2 * i + 1]), x3 = hi2(X[t][2 * i + 1]);
            float4 o;
            o.x = __fadd_rn(x0,  __fsub_rn(0.5f * cw.x, x0));
            o.y = __fadd_rn(x1,  __fsub_rn(0.5f * cw.y, x1));
            o.z = __fadd_rn(x2f, __fsub_rn(0.5f * cw.z, x2f));
            o.w = __fadd_rn(x3,  __fsub_rn(0.5f * cw.w, x3));
            ((float4*)op)[i] = o;
        }
    }
}

extern "C" void kernel_launch(void* const* d_in, const int* in_sizes, int n_in,
                              void* d_out, int out_size)
{
    const int*   ids  = (const int*)d_in[0];
    const float* wemb = (const float*)d_in[1];
    const float* cent = (const float*)d_in[2];
    float*       out  = (float*)d_out;
    int NI = in_sizes[0];   // 131072

    k1_moments<<<K1_BLOCKS, K1_THREADS>>>(ids, wemb, NI);
    k2a_reduce<<<K2A_BLOCKS, 256>>>();
    k2b1_reduce<<<(PSTRIDE + 255) / 256, 256>>>();
    k2b2_quad<<<D_SUB, KC>>>(cent, NI);
    k2b3_coeffs<<<1, KC>>>(NI);

    dim3 g3((NI + 511) / 512, D_SUB);
    k3_assign<<<g3, 256>>>(ids, wemb, cent, out, NI);
}

// round 6
// speedup vs baseline: 1.1284x; 1.0399x over previous
#include <cuda_runtime.h>
#include <cstdint>

#define D_SUB 8
#define KC 128
#define SUB 16
#define EMB 128

#define K1_BLOCKS 256
#define K1_THREADS 256
#define K1_WARPS (K1_BLOCKS * K1_THREADS / 32)   // 2048
#define PSTRIDE 2320                              // 8*(256 M +16 w +16 S1) + 16 p/q
#define K2A_BLOCKS 64
#define WARPS_PER_CHUNK (K1_WARPS / K2A_BLOCKS)   // 32

// scratch (no allocation allowed -> __device__ globals)
__device__ float  g_part[(size_t)K1_WARPS * PSTRIDE];
__device__ float  g_part2[(size_t)K2A_BLOCKS * PSTRIDE];
__device__ double g_mom[PSTRIDE];
__device__ double g_sumd[D_SUB * KC];
__device__ double g_ssqd[D_SUB * KC];
__device__ double g_ncv[D_SUB * KC];
__device__ float  g_G[KC];          // s_k
__device__ float  g_B[D_SUB * KC];  // -s_k*(normc_dk + mean_k)

// ---------- packed f32x2 helpers (k3 only) ----------
__device__ __forceinline__ unsigned long long pack2(float lo, float hi) {
    unsigned long long r;
    asm("mov.b64 %0, {%1, %2};" : "=l"(r) : "f"(lo), "f"(hi));
    return r;
}
__device__ __forceinline__ void fma2(unsigned long long& d, unsigned long long a, unsigned long long b) {
    asm("fma.rn.f32x2 %0, %1, %2, %0;" : "+l"(d) : "l"(a), "l"(b));
}
__device__ __forceinline__ unsigned long long fma2i(unsigned long long a, unsigned long long b, unsigned long long c) {
    unsigned long long r;
    asm("fma.rn.f32x2 %0, %1, %2, %3;" : "=l"(r) : "l"(a), "l"(b), "l"(c));
    return r;
}
__device__ __forceinline__ unsigned long long mul2(unsigned long long a, unsigned long long b) {
    unsigned long long r;
    asm("mul.rn.f32x2 %0, %1, %2;" : "=l"(r) : "l"(a), "l"(b));
    return r;
}
__device__ __forceinline__ unsigned long long add2(unsigned long long a, unsigned long long b) {
    unsigned long long r;
    asm("add.rn.f32x2 %0, %1, %2;" : "=l"(r) : "l"(a), "l"(b));
    return r;
}
__device__ __forceinline__ float lo2(unsigned long long v) { return __uint_as_float((unsigned)v); }
__device__ __forceinline__ float hi2(unsigned long long v) { return __uint_as_float((unsigned)(v >> 32)); }

// =====================================================================
// Kernel 1: per-warp moment accumulation (scalar form — measured faster
// than the packed-asm variant; compiler schedules freely).
// lane = 4*g + q : g = subspace d (0..7), q = row-quarter of M_d (0..3)
// Each lane accumulates a 4x16 block of M_d = sum x x^T, plus w, S1, p, q.
// =====================================================================
__global__ void k1_moments(const int* __restrict__ ids,
                           const float* __restrict__ wemb, int NI)
{
    int warp = (blockIdx.x * blockDim.x + threadIdx.x) >> 5;
    int lane = threadIdx.x & 31;
    int g = lane >> 2;   // subspace
    int q = lane & 3;    // row quarter

    float M[4][16];
#pragma unroll
    for (int r = 0; r < 4; r++)
#pragma unroll
        for (int j = 0; j < 16; j++) M[r][j] = 0.f;
    float wv[4] = {0.f, 0.f, 0.f, 0.f};
    float s1[4] = {0.f, 0.f, 0.f, 0.f};
    float pA = 0.f, qA = 0.f;

    for (int n = warp; n < NI; n += K1_WARPS) {
        int id = ids[n];
        const float4* xr = (const float4*)(wemb + (size_t)id * EMB + g * SUB);
        float4 a = xr[0], b = xr[1], c = xr[2], e = xr[3];
        float x[16] = {a.x, a.y, a.z, a.w, b.x, b.y, b.z, b.w,
                       c.x, c.y, c.z, c.w, e.x, e.y, e.z, e.w};
        float nx = 0.f;
#pragma unroll
        for (int i = 0; i < 16; i++) nx = fmaf(x[i], x[i], nx);

        float4 xq = (q == 0) ? a : ((q == 1) ? b : ((q == 2) ? c : e));
        float rv[4] = {xq.x, xq.y, xq.z, xq.w};
#pragma unroll
        for (int r = 0; r < 4; r++) {
#pragma unroll
            for (int j = 0; j < 16; j++) M[r][j] = fmaf(rv[r], x[j], M[r][j]);
            wv[r] = fmaf(rv[r], nx, wv[r]);
            s1[r] += rv[r];
        }
        if (q == 0) { pA += nx; qA = fmaf(nx, nx, qA); }
    }

    float* base = g_part + (size_t)warp * PSTRIDE + g * 288;
#pragma unroll
    for (int r = 0; r < 4; r++) {
#pragma unroll
        for (int j = 0; j < 16; j++)
            base[(4 * q + r) * 16 + j] = M[r][j];
        base[256 + 4 * q + r] = wv[r];
        base[272 + 4 * q + r] = s1[r];
    }
    if (q == 0) {
        g_part[(size_t)warp * PSTRIDE + 2304 + 2 * g]     = pA;
        g_part[(size_t)warp * PSTRIDE + 2304 + 2 * g + 1] = qA;
    }
}

// =====================================================================
// Kernel 2a: parallel deterministic reduction 2048 -> 64 partials
// =====================================================================
__global__ void k2a_reduce()
{
    int b = blockIdx.x;
    for (int idx = threadIdx.x; idx < PSTRIDE; idx += blockDim.x) {
        float s = 0.f;
        const float* p = g_part + (size_t)b * WARPS_PER_CHUNK * PSTRIDE + idx;
#pragma unroll 4
        for (int w = 0; w < WARPS_PER_CHUNK; w++) s += p[(size_t)w * PSTRIDE];
        g_part2[(size_t)b * PSTRIDE + idx] = s;
    }
}

// =====================================================================
// Kernel 2b1: fp64 final moment reduce (64 partials -> g_mom)
// =====================================================================
__global__ void k2b1_reduce()
{
    int idx = blockIdx.x * 256 + threadIdx.x;
    if (idx < PSTRIDE) {
        double s = 0.0;
        for (int b = 0; b < K2A_BLOCKS; b++)
            s += (double)g_part2[(size_t)b * PSTRIDE + idx];
        g_mom[idx] = s;
    }
}

// =====================================================================
// Kernel 2b2: per-(d,k) quadratic forms. One block per subspace d,
// one thread per k.
//  sum_dk = 2 S1.c - p_d - N*nc
//  ssq_dk = 4 c'Mc - 4(w.c + nc*S1.c) + (q_d + 2 nc p_d + N nc^2)
// =====================================================================
__global__ void k2b2_quad(const float* __restrict__ cent, int NI)
{
    __shared__ double Ms[288];
    __shared__ double pq[2];
    int d = blockIdx.x;
    int k = threadIdx.x;
    for (int i = k; i < 288; i += KC) Ms[i] = g_mom[d * 288 + i];
    if (k < 2) pq[k] = g_mom[2304 + 2 * d + k];
    __syncthreads();

    double cv[16];
    const float* c = cent + ((size_t)d * KC + k) * SUB;
#pragma unroll
    for (int i = 0; i < 16; i++) cv[i] = (double)c[i];
    double nc = 0.0, dotS = 0.0, dotw = 0.0, quad = 0.0;
#pragma unroll
    for (int i = 0; i < 16; i++) {
        nc   += cv[i] * cv[i];
        dotw += Ms[256 + i] * cv[i];
        dotS += Ms[272 + i] * cv[i];
        double row = 0.0;
#pragma unroll
        for (int j = 0; j < 16; j++) row += Ms[i * 16 + j] * cv[j];
        quad += cv[i] * row;
    }
    double cnt = (double)NI;
    double p = pq[0], qq = pq[1];
    g_sumd[d * KC + k] = 2.0 * dotS - p - cnt * nc;
    g_ssqd[d * KC + k] = 4.0 * quad - 4.0 * (dotw + nc * dotS) + (qq + 2.0 * nc * p + cnt * nc * nc);
    g_ncv[d * KC + k]  = nc;
}

// =====================================================================
// Kernel 2b3: combine over d (fixed order), BN coefficients.
// =====================================================================
__global__ void k2b3_coeffs(int NI)
{
    int k = threadIdx.x;
    double sum = 0.0, ssq = 0.0;
#pragma unroll
    for (int d = 0; d < D_SUB; d++) {
        sum += g_sumd[d * KC + k];
        ssq += g_ssqd[d * KC + k];
    }
    double tot  = (double)NI * (double)D_SUB;
    double mean = sum / tot;
    double var  = ssq / tot - mean * mean;
    double s    = 1.0 / sqrt(var + 0.001);
    g_G[k] = (float)s;
#pragma unroll
    for (int d = 0; d < D_SUB; d++)
        g_B[d * KC + k] = (float)(-s * (g_ncv[d * KC + k] + mean));
}

// =====================================================================
// Kernel 3: thread-per-(n,d) x 2 tokens, 2*centroids in SMEM.
// Dual accumulators halve the FMA2 dependency chain; -||x||^2 folded
// into the first FMA2's addend; score = s*dotsum + B (1 FFMA).
// =====================================================================
__global__ void __launch_bounds__(256, 3)
k3_assign(const int* __restrict__ ids,
          const float* __restrict__ wemb,
          const float* __restrict__ cent,
          float* __restrict__ out, int NI)
{
    __shared__ float cs[KC][20];   // [k]: 2*c[16], s, B, pad2

    int tid = threadIdx.x;
    int d = blockIdx.y;

    for (int i = tid; i < KC * SUB; i += 256) {
        int k = i >> 4, j = i & 15;
        cs[k][j] = 2.0f * cent[((size_t)(d * KC + k)) * SUB + j];
    }
    if (tid < KC) {
        cs[tid][16] = g_G[tid];
        cs[tid][17] = g_B[d * KC + tid];
    }
    __syncthreads();

    int base = blockIdx.x * 512 + tid;
    int n[2] = {base, base + 256};

    unsigned long long X[2][8];
    unsigned long long nxp[2];
    float best[2];
    int bk[2];
    bool valid[2];

#pragma unroll
    for (int t = 0; t < 2; t++) {
        valid[t] = (n[t] < NI);
        int id = valid[t] ? ids[n[t]] : 0;
        const ulonglong2* xp = (const ulonglong2*)(wemb + (size_t)id * EMB + d * SUB);
        ulonglong2 v0 = xp[0], v1 = xp[1], v2 = xp[2], v3 = xp[3];
        X[t][0] = v0.x; X[t][1] = v0.y; X[t][2] = v1.x; X[t][3] = v1.y;
        X[t][4] = v2.x; X[t][5] = v2.y; X[t][6] = v3.x; X[t][7] = v3.y;
        unsigned long long na = mul2(X[t][0], X[t][0]);
        unsigned long long nb = mul2(X[t][1], X[t][1]);
#pragma unroll
        for (int p = 2; p < 8; p += 2) { fma2(na, X[t][p], X[t][p]); fma2(nb, X[t][p + 1], X[t][p + 1]); }
        na = add2(na, nb);
        nxp[t] = pack2(-(lo2(na) + hi2(na)), 0.0f);
        best[t] = -3.4e38f;
        bk[t] = 0;
    }

#pragma unroll 4
    for (int k = 0; k < KC; k++) {
        const ulonglong2* cp = (const ulonglong2*)&cs[k][0];
        ulonglong2 c0 = cp[0], c1 = cp[1], c2v = cp[2], c3 = cp[3];
        unsigned long long C[8] = {c0.x, c0.y, c1.x, c1.y, c2v.x, c2v.y, c3.x, c3.y};
        float2 sb = *(const float2*)&cs[k][16];
#pragma unroll
        for (int t = 0; t < 2; t++) {
            unsigned long long a0 = fma2i(X[t][0], C[0], nxp[t]);   // x*2c - ||x||^2 seed
            unsigned long long a1 = mul2(X[t][1], C[1]);
            fma2(a0, X[t][2], C[2]);
            fma2(a1, X[t][3], C[3]);
            fma2(a0, X[t][4], C[4]);
            fma2(a1, X[t][5], C[5]);
            fma2(a0, X[t][6], C[6]);
            fma2(a1, X[t][7], C[7]);
            a0 = add2(a0, a1);
            float ds = lo2(a0) + hi2(a0);
            float sc = fmaf(sb.x, ds, sb.y);
            if (sc > best[t]) { best[t] = sc; bk[t] = k; }
        }
    }

#pragma unroll
    for (int t = 0; t < 2; t++) {
        if (!valid[t]) continue;
        const float4* cg = (const float4*)&cs[bk[t]][0];
        float* op = out + (size_t)n[t] * EMB + d * SUB;
#pragma unroll
        for (int i = 0; i < 4; i++) {
            float4 cw = cg[i];
            float x0 = lo2(X[t][2 * i]),     x1 = hi2(X[t][2 * i]);
            float x2f = lo2(X[t][2 * i + 1]), x3 = hi2(X[t][2 * i + 1]);
            float4 o;
            o.x = __fadd_rn(x0,  __fsub_rn(0.5f * cw.x, x0));
            o.y = __fadd_rn(x1,  __fsub_rn(0.5f * cw.y, x1));
            o.z = __fadd_rn(x2f, __fsub_rn(0.5f * cw.z, x2f));
            o.w = __fadd_rn(x3,  __fsub_rn(0.5f * cw.w, x3));
            ((float4*)op)[i] = o;
        }
    }
}

extern "C" void kernel_launch(void* const* d_in, const int* in_sizes, int n_in,
                              void* d_out, int out_size)
{
    const int*   ids  = (const int*)d_in[0];
    const float* wemb = (const float*)d_in[1];
    const float* cent = (const float*)d_in[2];
    float*       out  = (float*)d_out;
    int NI = in_sizes[0];   // 131072

    k1_moments<<<K1_BLOCKS, K1_THREADS>>>(ids, wemb, NI);
    k2a_reduce<<<K2A_BLOCKS, 256>>>();
    k2b1_reduce<<<(PSTRIDE + 255) / 256, 256>>>();
    k2b2_quad<<<D_SUB, KC>>>(cent, NI);
    k2b3_coeffs<<<1, KC>>>(NI);

    dim3 g3((NI + 511) / 512, D_SUB);
    k3_assign<<<g3, 256>>>(ids, wemb, cent, out, NI);
}

// round 7
// speedup vs baseline: 1.1372x; 1.0079x over previous
#include <cuda_runtime.h>
#include <cstdint>

#define D_SUB 8
#define KC 128
#define SUB 16
#define EMB 128

#define K1_BLOCKS 256
#define K1_THREADS 256
#define K1_WARPS (K1_BLOCKS * K1_THREADS / 32)   // 2048
#define PSTRIDE 2320                              // 8*(256 M +16 w +16 S1) + 16 p/q
#define K2A_BLOCKS 64
#define WARPS_PER_CHUNK (K1_WARPS / K2A_BLOCKS)   // 32

// scratch (no allocation allowed -> __device__ globals)
__device__ float  g_part[(size_t)K1_WARPS * PSTRIDE];
__device__ float  g_part2[(size_t)K2A_BLOCKS * PSTRIDE];
__device__ double g_mom[PSTRIDE];
__device__ double g_sumd[D_SUB * KC];
__device__ double g_ssqd[D_SUB * KC];
__device__ double g_ncv[D_SUB * KC];
__device__ float  g_G[KC];          // s_k
__device__ float  g_B[D_SUB * KC];  // -s_k*(normc_dk + mean_k)

// ---------- packed f32x2 helpers (k3 only) ----------
__device__ __forceinline__ unsigned long long pack2(float lo, float hi) {
    unsigned long long r;
    asm("mov.b64 %0, {%1, %2};" : "=l"(r) : "f"(lo), "f"(hi));
    return r;
}
__device__ __forceinline__ void fma2(unsigned long long& d, unsigned long long a, unsigned long long b) {
    asm("fma.rn.f32x2 %0, %1, %2, %0;" : "+l"(d) : "l"(a), "l"(b));
}
__device__ __forceinline__ unsigned long long fma2i(unsigned long long a, unsigned long long b, unsigned long long c) {
    unsigned long long r;
    asm("fma.rn.f32x2 %0, %1, %2, %3;" : "=l"(r) : "l"(a), "l"(b), "l"(c));
    return r;
}
__device__ __forceinline__ unsigned long long mul2(unsigned long long a, unsigned long long b) {
    unsigned long long r;
    asm("mul.rn.f32x2 %0, %1, %2;" : "=l"(r) : "l"(a), "l"(b));
    return r;
}
__device__ __forceinline__ unsigned long long add2(unsigned long long a, unsigned long long b) {
    unsigned long long r;
    asm("add.rn.f32x2 %0, %1, %2;" : "=l"(r) : "l"(a), "l"(b));
    return r;
}
__device__ __forceinline__ float lo2(unsigned long long v) { return __uint_as_float((unsigned)v); }
__device__ __forceinline__ float hi2(unsigned long long v) { return __uint_as_float((unsigned)(v >> 32)); }

// =====================================================================
// Kernel 1: per-warp moment accumulation (scalar form — measured faster
// than the packed-asm variant; compiler schedules freely).
// lane = 4*g + q : g = subspace d (0..7), q = row-quarter of M_d (0..3)
// Each lane accumulates a 4x16 block of M_d = sum x x^T, plus w, S1, p, q.
// =====================================================================
__global__ void k1_moments(const int* __restrict__ ids,
                           const float* __restrict__ wemb, int NI)
{
    int warp = (blockIdx.x * blockDim.x + threadIdx.x) >> 5;
    int lane = threadIdx.x & 31;
    int g = lane >> 2;   // subspace
    int q = lane & 3;    // row quarter

    float M[4][16];
#pragma unroll
    for (int r = 0; r < 4; r++)
#pragma unroll
        for (int j = 0; j < 16; j++) M[r][j] = 0.f;
    float wv[4] = {0.f, 0.f, 0.f, 0.f};
    float s1[4] = {0.f, 0.f, 0.f, 0.f};
    float pA = 0.f, qA = 0.f;

    for (int n = warp; n < NI; n += K1_WARPS) {
        int id = ids[n];
        const float4* xr = (const float4*)(wemb + (size_t)id * EMB + g * SUB);
        float4 a = xr[0], b = xr[1], c = xr[2], e = xr[3];
        float x[16] = {a.x, a.y, a.z, a.w, b.x, b.y, b.z, b.w,
                       c.x, c.y, c.z, c.w, e.x, e.y, e.z, e.w};
        float nx = 0.f;
#pragma unroll
        for (int i = 0; i < 16; i++) nx = fmaf(x[i], x[i], nx);

        float4 xq = (q == 0) ? a : ((q == 1) ? b : ((q == 2) ? c : e));
        float rv[4] = {xq.x, xq.y, xq.z, xq.w};
#pragma unroll
        for (int r = 0; r < 4; r++) {
#pragma unroll
            for (int j = 0; j < 16; j++) M[r][j] = fmaf(rv[r], x[j], M[r][j]);
            wv[r] = fmaf(rv[r], nx, wv[r]);
            s1[r] += rv[r];
        }
        if (q == 0) { pA += nx; qA = fmaf(nx, nx, qA); }
    }

    float* base = g_part + (size_t)warp * PSTRIDE + g * 288;
#pragma unroll
    for (int r = 0; r < 4; r++) {
#pragma unroll
        for (int j = 0; j < 16; j++)
            base[(4 * q + r) * 16 + j] = M[r][j];
        base[256 + 4 * q + r] = wv[r];
        base[272 + 4 * q + r] = s1[r];
    }
    if (q == 0) {
        g_part[(size_t)warp * PSTRIDE + 2304 + 2 * g]     = pA;
        g_part[(size_t)warp * PSTRIDE + 2304 + 2 * g + 1] = qA;
    }
}

// =====================================================================
// Kernel 2a: parallel deterministic reduction 2048 -> 64 partials
// =====================================================================
__global__ void k2a_reduce()
{
    int b = blockIdx.x;
    for (int idx = threadIdx.x; idx < PSTRIDE; idx += blockDim.x) {
        float s = 0.f;
        const float* p = g_part + (size_t)b * WARPS_PER_CHUNK * PSTRIDE + idx;
#pragma unroll 4
        for (int w = 0; w < WARPS_PER_CHUNK; w++) s += p[(size_t)w * PSTRIDE];
        g_part2[(size_t)b * PSTRIDE + idx] = s;
    }
}

// =====================================================================
// Kernel 2b1: fp64 final moment reduce (64 partials -> g_mom)
// =====================================================================
__global__ void k2b1_reduce()
{
    int idx = blockIdx.x * 256 + threadIdx.x;
    if (idx < PSTRIDE) {
        double s = 0.0;
        for (int b = 0; b < K2A_BLOCKS; b++)
            s += (double)g_part2[(size_t)b * PSTRIDE + idx];
        g_mom[idx] = s;
    }
}

// =====================================================================
// Kernel 2b2: per-(d,k) quadratic forms. One block per subspace d,
// one thread per k.
//  sum_dk = 2 S1.c - p_d - N*nc
//  ssq_dk = 4 c'Mc - 4(w.c + nc*S1.c) + (q_d + 2 nc p_d + N nc^2)
// =====================================================================
__global__ void k2b2_quad(const float* __restrict__ cent, int NI)
{
    __shared__ double Ms[288];
    __shared__ double pq[2];
    int d = blockIdx.x;
    int k = threadIdx.x;
    for (int i = k; i < 288; i += KC) Ms[i] = g_mom[d * 288 + i];
    if (k < 2) pq[k] = g_mom[2304 + 2 * d + k];
    __syncthreads();

    double cv[16];
    const float* c = cent + ((size_t)d * KC + k) * SUB;
#pragma unroll
    for (int i = 0; i < 16; i++) cv[i] = (double)c[i];
    double nc = 0.0, dotS = 0.0, dotw = 0.0, quad = 0.0;
#pragma unroll
    for (int i = 0; i < 16; i++) {
        nc   += cv[i] * cv[i];
        dotw += Ms[256 + i] * cv[i];
        dotS += Ms[272 + i] * cv[i];
        double row = 0.0;
#pragma unroll
        for (int j = 0; j < 16; j++) row += Ms[i * 16 + j] * cv[j];
        quad += cv[i] * row;
    }
    double cnt = (double)NI;
    double p = pq[0], qq = pq[1];
    g_sumd[d * KC + k] = 2.0 * dotS - p - cnt * nc;
    g_ssqd[d * KC + k] = 4.0 * quad - 4.0 * (dotw + nc * dotS) + (qq + 2.0 * nc * p + cnt * nc * nc);
    g_ncv[d * KC + k]  = nc;
}

// =====================================================================
// Kernel 2b3: combine over d (fixed order), BN coefficients.
// =====================================================================
__global__ void k2b3_coeffs(int NI)
{
    int k = threadIdx.x;
    double sum = 0.0, ssq = 0.0;
#pragma unroll
    for (int d = 0; d < D_SUB; d++) {
        sum += g_sumd[d * KC + k];
        ssq += g_ssqd[d * KC + k];
    }
    double tot  = (double)NI * (double)D_SUB;
    double mean = sum / tot;
    double var  = ssq / tot - mean * mean;
    double s    = 1.0 / sqrt(var + 0.001);
    g_G[k] = (float)s;
#pragma unroll
    for (int d = 0; d < D_SUB; d++)
        g_B[d * KC + k] = (float)(-s * (g_ncv[d * KC + k] + mean));
}

// =====================================================================
// Kernel 3: thread-per-(n,d) x 2 tokens, 2*centroids in SMEM.
// Dual accumulators halve the FMA2 dependency chain; -||x||^2 folded
// into the first FMA2's addend; score = s*dotsum + B (1 FFMA).
// =====================================================================
__global__ void __launch_bounds__(256, 3)
k3_assign(const int* __restrict__ ids,
          const float* __restrict__ wemb,
          const float* __restrict__ cent,
          float* __restrict__ out, int NI)
{
    __shared__ float cs[KC][20];   // [k]: 2*c[16], s, B, pad2

    int tid = threadIdx.x;
    int d = blockIdx.y;

    for (int i = tid; i < KC * SUB; i += 256) {
        int k = i >> 4, j = i & 15;
        cs[k][j] = 2.0f * cent[((size_t)(d * KC + k)) * SUB + j];
    }
    if (tid < KC) {
        cs[tid][16] = g_G[tid];
        cs[tid][17] = g_B[d * KC + tid];
    }
    __syncthreads();

    int base = blockIdx.x * 512 + tid;
    int n[2] = {base, base + 256};

    unsigned long long X[2][8];
    unsigned long long nxp[2];
    float best[2];
    int bk[2];
    bool valid[2];

#pragma unroll
    for (int t = 0; t < 2; t++) {
        valid[t] = (n[t] < NI);
        int id = valid[t] ? ids[n[t]] : 0;
        const ulonglong2* xp = (const ulonglong2*)(wemb + (size_t)id * EMB + d * SUB);
        ulonglong2 v0 = xp[0], v1 = xp[1], v2 = xp[2], v3 = xp[3];
        X[t][0] = v0.x; X[t][1] = v0.y; X[t][2] = v1.x; X[t][3] = v1.y;
        X[t][4] = v2.x; X[t][5] = v2.y; X[t][6] = v3.x; X[t][7] = v3.y;
        unsigned long long na = mul2(X[t][0], X[t][0]);
        unsigned long long nb = mul2(X[t][1], X[t][1]);
#pragma unroll
        for (int p = 2; p < 8; p += 2) { fma2(na, X[t][p], X[t][p]); fma2(nb, X[t][p + 1], X[t][p + 1]); }
        na = add2(na, nb);
        nxp[t] = pack2(-(lo2(na) + hi2(na)), 0.0f);
        best[t] = -3.4e38f;
        bk[t] = 0;
    }

#pragma unroll 4
    for (int k = 0; k < KC; k++) {
        const ulonglong2* cp = (const ulonglong2*)&cs[k][0];
        ulonglong2 c0 = cp[0], c1 = cp[1], c2v = cp[2], c3 = cp[3];
        unsigned long long C[8] = {c0.x, c0.y, c1.x, c1.y, c2v.x, c2v.y, c3.x, c3.y};
        float2 sb = *(const float2*)&cs[k][16];
#pragma unroll
        for (int t = 0; t < 2; t++) {
            unsigned long long a0 = fma2i(X[t][0], C[0], nxp[t]);   // x*2c - ||x||^2 seed
            unsigned long long a1 = mul2(X[t][1], C[1]);
            fma2(a0, X[t][2], C[2]);
            fma2(a1, X[t][3], C[3]);
            fma2(a0, X[t][4], C[4]);
            fma2(a1, X[t][5], C[5]);
            fma2(a0, X[t][6], C[6]);
            fma2(a1, X[t][7], C[7]);
            a0 = add2(a0, a1);
            float ds = lo2(a0) + hi2(a0);
            float sc = fmaf(sb.x, ds, sb.y);
            if (sc > best[t]) { best[t] = sc; bk[t] = k; }
        }
    }

#pragma unroll
    for (int t = 0; t < 2; t++) {
        if (!valid[t]) continue;
        const float4* cg = (const float4*)&cs[bk[t]][0];
        float* op = out + (size_t)n[t] * EMB + d * SUB;
#pragma unroll
        for (int i = 0; i < 4; i++) {
            float4 cw = cg[i];
            float x0 = lo2(X[t][2 * i]),     x1 = hi2(X[t][2 * i]);
            float x2f = lo2(X[t][2 * i + 1]), x3 = hi2(X[t][2 * i + 1]);
            float4 o;
            o.x = __fadd_rn(x0,  __fsub_rn(0.5f * cw.x, x0));
            o.y = __fadd_rn(x1,  __fsub_rn(0.5f * cw.y, x1));
            o.z = __fadd_rn(x2f, __fsub_rn(0.5f * cw.z, x2f));
            o.w = __fadd_rn(x3,  __fsub_rn(0.5f * cw.w, x3));
            ((float4*)op)[i] = o;
        }
    }
}

extern "C" void kernel_launch(void* const* d_in, const int* in_sizes, int n_in,
                              void* d_out, int out_size)
{
    const int*   ids  = (const int*)d_in[0];
    const float* wemb = (const float*)d_in[1];
    const float* cent = (const float*)d_in[2];
    float*       out  = (float*)d_out;
    int NI = in_sizes[0];   // 131072

    k1_moments<<<K1_BLOCKS, K1_THREADS>>>(ids, wemb, NI);
    k2a_reduce<<<K2A_BLOCKS, 256>>>();
    k2b1_reduce<<<(PSTRIDE + 255) / 256, 256>>>();
    k2b2_quad<<<D_SUB, KC>>>(cent, NI);
    k2b3_coeffs<<<1, KC>>>(NI);

    dim3 g3((NI + 511) / 512, D_SUB);
    k3_assign<<<g3, 256>>>(ids, wemb, cent, out, NI);
}